// round 5
// baseline (speedup 1.0000x reference)
#include <cuda_runtime.h>
#include <cstdint>

// Autoregressive RNN, HIDDEN=4096, STEPS=2048. 128 persistent CTAs x 512 thr.
// CTA owns 32 rows of W_hh. Per warp: 512-col slice x 16 rows.
// Tiers per slice: cols [0,128) regs (64/lane), [128,320) smem float2,
// [320,512) streamed from L2 float2 (prefetched before the wait).
// Dataflow sync: per-CTA monotonic tag; each warp polls ONLY its 8 producer
// CTAs; h rotates over 3 buffers (proof: writer of step t+2 needed all 128
// tags >= t+2, so every reader finished step t). No poll warp, no smem spins.

#define HIDDEN 4096
#define STEPS  2048
#define NCTA   128
#define ROWS   32
#define NTH    512

__device__ unsigned int g_tag[NCTA];     // monotonic across graph replays
__device__ float g_h3[3][HIDDEN];        // hidden state, 3-buffer rotation
__device__ float g_party[2][NCTA];       // per-CTA partials of W_out . h

__device__ __forceinline__ unsigned int ld_cg_u32_volatile(const unsigned int* p) {
    unsigned int v;
    asm volatile("ld.global.cg.b32 %0, [%1];" : "=r"(v) : "l"(p) : "memory");
    return v;
}
__device__ __forceinline__ uint4 ld_cg_v4_volatile(const uint4* p) {
    uint4 v;
    asm volatile("ld.global.cg.v4.b32 {%0,%1,%2,%3}, [%4];"
                 : "=r"(v.x), "=r"(v.y), "=r"(v.z), "=r"(v.w)
                 : "l"(p) : "memory");
    return v;
}

__global__ __launch_bounds__(NTH, 1)
void rnn_kernel(const float* __restrict__ inputs,
                const float* __restrict__ W_ih,
                const float* __restrict__ W_hh,
                const float* __restrict__ b_ih,
                const float* __restrict__ b_hh,
                const float* __restrict__ W_out,
                const float* __restrict__ b_out,
                float* __restrict__ out, int out_size)
{
    extern __shared__ float smem[];
    float2* sw2   = (float2*)smem;                    // [16][3][16][32] float2
    float*  h_sw  = smem + 2 * (16 * 3 * 16 * 32);    // 4096 floats
    float*  s_part = h_sw + HIDDEN;                   // [2][32][8]

    const int tid = threadIdx.x;
    const int w   = tid >> 5;
    const int l   = tid & 31;
    const int g   = w >> 3;        // 0/1: row half (quarters 2g, 2g+1)
    const int c   = w & 7;         // column slice
    const int cta = blockIdx.x;
    const int RB  = cta * ROWS + g * 16;
    const int c512 = c * 512;

    const unsigned int base = __ldcg(&g_tag[cta]);

    // ---- register tier: cols [c512, c512+128) ----
    float wreg[64];
    #pragma unroll
    for (int i = 0; i < 4; i++)
        #pragma unroll
        for (int j = 0; j < 16; j++)
            wreg[i * 16 + j] = W_hh[(size_t)(RB + j) * HIDDEN + c512 + i * 32 + l];

    // ---- shared tier: cols [c512+128, c512+320), float2 layout ----
    for (int it = 0; it < 3; it++)
        for (int j = 0; j < 16; j++) {
            const float* p = W_hh + (size_t)(RB + j) * HIDDEN + c512 + 128 + it * 64 + 2 * l;
            sw2[((w * 3 + it) * 16 + j) * 32 + l] = make_float2(p[0], p[1]);
        }

    for (int idx = tid; idx < HIDDEN; idx += NTH) h_sw[idx] = 0.f;   // h_{-1}=0

    float f_wih = 0.f, f_b = 0.f, f_wout = 0.f;
    if (w == 0) {
        int R  = cta * ROWS + l;
        f_wih  = W_ih[R];
        f_b    = b_ih[R] + b_hh[R];
        f_wout = W_out[R];
    }
    const float bo = b_out[0];
    const float x0 = inputs[0];
    // streamed tier base: cols [c512+320, c512+512)
    const float2* wg2 = (const float2*)(W_hh + (size_t)RB * HIDDEN + c512 + 320) + l;

    __syncthreads();

    #pragma unroll 1
    for (int t = 0; t < STEPS; t++) {
        // prefetch streamed chunk it=0 (h-independent; lands during the wait)
        float2 buf[16];
        #pragma unroll
        for (int j = 0; j < 16; j++) buf[j] = __ldcg(wg2 + (size_t)j * (HIDDEN / 2));

        float x = x0;                  // meaningful only in warp 0

        if (t > 0) {
            // poll ONLY this warp's 8 producer CTAs (lanes duplicated 4x)
            const unsigned int tgt = base + (unsigned)t;
            const unsigned int* tp = &g_tag[c * 16 + g * 8 + (l & 7)];
            for (;;) {
                unsigned int v = ld_cg_u32_volatile(tp);
                if (__all_sync(0xffffffffu, v >= tgt)) break;
                __nanosleep(30);
            }
            // stage this warp's two h quarters (float4)
            const float4* hb4 = (const float4*)(g_h3[(t - 1) % 3] + c512);
            float4* hs4 = (float4*)(h_sw + c512);
            int q0 = g * 2;
            float4 v0 = __ldcg(hb4 + q0 * 32 + l);
            float4 v1 = __ldcg(hb4 + (q0 + 1) * 32 + l);
            hs4[q0 * 32 + l] = v0;
            hs4[(q0 + 1) * 32 + l] = v1;
        }
        // pair barrier: warps c and c+8
        asm volatile("bar.sync %0, 64;" :: "r"(1 + c) : "memory");

        // finisher gathers x = y_{t-1} (tags are set by now; near-instant poll)
        if (w == 0 && t > 0) {
            const unsigned int tgt = base + (unsigned)t;
            const uint4* tp = (const uint4*)g_tag;
            for (;;) {
                uint4 v = ld_cg_v4_volatile(tp + l);
                bool ok = (v.x >= tgt) & (v.y >= tgt) & (v.z >= tgt) & (v.w >= tgt);
                if (__all_sync(0xffffffffu, ok)) break;
                __nanosleep(30);
            }
            const float* py = g_party[(t - 1) & 1];
            float pv = __ldcg(py + l) + __ldcg(py + 32 + l)
                     + __ldcg(py + 64 + l) + __ldcg(py + 96 + l);
            pv += __shfl_xor_sync(0xffffffffu, pv, 16);
            pv += __shfl_xor_sync(0xffffffffu, pv, 8);
            pv += __shfl_xor_sync(0xffffffffu, pv, 4);
            pv += __shfl_xor_sync(0xffffffffu, pv, 2);
            pv += __shfl_xor_sync(0xffffffffu, pv, 1);
            x = bo + pv;
            if (cta == 0 && l == 0) out[t - 1] = x;      // ys[t-1]
        }

        // ---- matvec: 16 rows x 512-col slice ----
        float acc[16];
        #pragma unroll
        for (int j = 0; j < 16; j++) acc[j] = 0.f;

        // register tier (cols 0..127)
        #pragma unroll
        for (int i = 0; i < 4; i++) {
            float hv = h_sw[c512 + i * 32 + l];
            #pragma unroll
            for (int j = 0; j < 16; j++) acc[j] = fmaf(wreg[i * 16 + j], hv, acc[j]);
        }

        const float2* h2s = (const float2*)(h_sw + c512 + 128);
        const float2* h2g = (const float2*)(h_sw + c512 + 320);
        #pragma unroll
        for (int it = 0; it < 3; it++) {
            // streamed tier iteration
            float2 hg = h2g[it * 32 + l];
            #pragma unroll
            for (int j = 0; j < 16; j++) {
                acc[j] = fmaf(buf[j].x, hg.x, acc[j]);
                acc[j] = fmaf(buf[j].y, hg.y, acc[j]);
            }
            if (it < 2) {
                #pragma unroll
                for (int j = 0; j < 16; j++)
                    buf[j] = __ldcg(wg2 + (it + 1) * 32 + (size_t)j * (HIDDEN / 2));
            }
            // shared tier iteration
            float2 hs = h2s[it * 32 + l];
            #pragma unroll
            for (int j = 0; j < 16; j++) {
                float2 wv = sw2[((w * 3 + it) * 16 + j) * 32 + l];
                acc[j] = fmaf(wv.x, hs.x, acc[j]);
                acc[j] = fmaf(wv.y, hs.y, acc[j]);
            }
        }

        // warp reduce each row partial -> s_part[t&1]
        float* spb = s_part + (t & 1) * 256;
        #pragma unroll
        for (int j = 0; j < 16; j++) {
            float v = acc[j];
            v += __shfl_xor_sync(0xffffffffu, v, 16);
            v += __shfl_xor_sync(0xffffffffu, v, 8);
            v += __shfl_xor_sync(0xffffffffu, v, 4);
            v += __shfl_xor_sync(0xffffffffu, v, 2);
            v += __shfl_xor_sync(0xffffffffu, v, 1);
            if (l == 0) spb[(g * 16 + j) * 8 + c] = v;
        }
        __syncthreads();

        // ---- finisher: combine, tanh, publish, release, tag ----
        if (w == 0) {
            const float4* sp4 = (const float4*)(s_part + (t & 1) * 256 + l * 8);
            float4 a = sp4[0], b4 = sp4[1];
            float dot = ((a.x + a.y) + (a.z + a.w)) + ((b4.x + b4.y) + (b4.z + b4.w));
            float pre  = fmaf(x, f_wih, f_b + dot);
            float hnew = tanhf(pre);
            __stcg(&g_h3[t % 3][cta * ROWS + l], hnew);

            float pv = hnew * f_wout;
            pv += __shfl_xor_sync(0xffffffffu, pv, 16);
            pv += __shfl_xor_sync(0xffffffffu, pv, 8);
            pv += __shfl_xor_sync(0xffffffffu, pv, 4);
            pv += __shfl_xor_sync(0xffffffffu, pv, 2);
            pv += __shfl_xor_sync(0xffffffffu, pv, 1);
            if (l == 0) __stcg(&g_party[t & 1][cta], pv);

            if (t == STEPS - 1 && out_size >= STEPS + HIDDEN)
                out[STEPS + cta * ROWS + l] = hnew;

            __syncwarp();
            asm volatile("fence.acq_rel.gpu;" ::: "memory");   // producer release
            if (l == 0) __stcg(&g_tag[cta], base + (unsigned)t + 1u);
        }
    }

    // final readout ys[STEPS-1]
    if (cta == 0 && w == 0) {
        const unsigned int tgt = base + (unsigned)STEPS;
        const uint4* tp = (const uint4*)g_tag;
        for (;;) {
            uint4 v = ld_cg_v4_volatile(tp + l);
            bool ok = (v.x >= tgt) & (v.y >= tgt) & (v.z >= tgt) & (v.w >= tgt);
            if (__all_sync(0xffffffffu, ok)) break;
            __nanosleep(30);
        }
        asm volatile("" ::: "memory");
        const float* py = g_party[(STEPS - 1) & 1];
        float pv = __ldcg(py + l) + __ldcg(py + 32 + l)
                 + __ldcg(py + 64 + l) + __ldcg(py + 96 + l);
        pv += __shfl_xor_sync(0xffffffffu, pv, 16);
        pv += __shfl_xor_sync(0xffffffffu, pv, 8);
        pv += __shfl_xor_sync(0xffffffffu, pv, 4);
        pv += __shfl_xor_sync(0xffffffffu, pv, 2);
        pv += __shfl_xor_sync(0xffffffffu, pv, 1);
        if (l == 0) out[STEPS - 1] = bo + pv;
    }
}

extern "C" void kernel_launch(void* const* d_in, const int* in_sizes, int n_in,
                              void* d_out, int out_size)
{
    const float* inputs = (const float*)d_in[0];
    const float* W_ih   = (const float*)d_in[1];
    const float* W_hh   = (const float*)d_in[2];
    const float* b_ih   = (const float*)d_in[3];
    const float* b_hh   = (const float*)d_in[4];
    const float* W_out  = (const float*)d_in[5];
    const float* b_out  = (const float*)d_in[6];
    float* out = (float*)d_out;

    // smem: weights 192KB + h 16KB + partials 2KB + pad
    const int smem_bytes = (2 * 16 * 3 * 16 * 32 + HIDDEN + 2 * 32 * 8 + 8)
                           * (int)sizeof(float);
    cudaFuncSetAttribute(rnn_kernel,
                         cudaFuncAttributeMaxDynamicSharedMemorySize, smem_bytes);

    rnn_kernel<<<NCTA, NTH, smem_bytes>>>(
        inputs, W_ih, W_hh, b_ih, b_hh, W_out, b_out, out, out_size);
}

// round 8
// speedup vs baseline: 1.3746x; 1.3746x over previous
#include <cuda_runtime.h>
#include <cstdint>

// Autoregressive RNN, HIDDEN=4096, STEPS=2048.
// 128 persistent CTAs x 1024 threads (32 warps -> occupancy 50%, 8/SMSP).
// Warp (rg,c): 8 rows x 512-col slice. Weight tiers per slice:
//   cols [0,64)    float2 regs (16 regs)
//   cols [64,256)  smem float2 (196KB/CTA)
//   cols [256,512) streamed from L2 float2 (~33MB/step chip-wide)
// Sync (proven R4 skeleton): per-CTA monotonic tag; poll warp w31 scans all
// 128 tags (uint4/lane), releases via volatile smem epoch; finisher w0
// gathers y-partials, computes tanh, publishes h + tag.

#define HIDDEN 4096
#define STEPS  2048
#define NCTA   128
#define NTH    1024
#define H2     (HIDDEN / 2)

__device__ unsigned g_tag[NCTA];       // monotonic across graph replays
__device__ float g_h[2][HIDDEN];       // hidden state ping-pong
__device__ float g_party[2][NCTA];     // per-CTA partials of W_out . h

__device__ __forceinline__ uint4 ld_vol_v4(const uint4* p) {
    uint4 v;
    asm volatile("ld.global.cg.v4.b32 {%0,%1,%2,%3}, [%4];"
                 : "=r"(v.x), "=r"(v.y), "=r"(v.z), "=r"(v.w)
                 : "l"(p) : "memory");
    return v;
}

__global__ __launch_bounds__(NTH, 1)
void rnn_kernel(const float* __restrict__ inputs,
                const float* __restrict__ W_ih,
                const float* __restrict__ W_hh,
                const float* __restrict__ b_ih,
                const float* __restrict__ b_hh,
                const float* __restrict__ W_out,
                const float* __restrict__ b_out,
                float* __restrict__ out, int out_size)
{
    extern __shared__ float smem[];
    float2* sw2   = (float2*)smem;                    // [32][3][8][32] float2
    float*  h_sw  = smem + 2 * (32 * 3 * 8 * 32);     // 4096 floats
    float*  s_part = h_sw + HIDDEN;                   // [2][256]
    float*  s_x    = s_part + 512;                    // [1] (+pad)
    volatile unsigned* s_ready = (volatile unsigned*)(s_x + 4);

    const int tid = threadIdx.x;
    const int w   = tid >> 5;
    const int l   = tid & 31;
    const int rg  = w >> 3;        // row group 0..3 (8 rows each)
    const int c   = w & 7;         // column slice 0..7 (512 cols)
    const int cta = blockIdx.x;
    const int RB  = cta * 32 + rg * 8;
    const int c512 = c * 512;

    if (tid == 0) s_ready[0] = 0u;
    const unsigned base = __ldcg(&g_tag[cta]);

    // ---- register tier: cols [c512, c512+64), float2 ----
    float2 wreg[8];
    #pragma unroll
    for (int j = 0; j < 8; j++)
        wreg[j] = *(const float2*)&W_hh[(size_t)(RB + j) * HIDDEN + c512 + 2 * l];

    // ---- shared tier: cols [c512+64, c512+256), 3 float2-iters ----
    for (int s = 0; s < 3; s++)
        for (int j = 0; j < 8; j++)
            sw2[((w * 3 + s) * 8 + j) * 32 + l] =
                *(const float2*)&W_hh[(size_t)(RB + j) * HIDDEN + c512 + 64 + 64 * s + 2 * l];

    for (int idx = tid; idx < HIDDEN; idx += NTH) h_sw[idx] = 0.f;   // h_{-1}=0

    float f_wih = 0.f, f_b = 0.f, f_wout = 0.f;
    if (w == 0) {
        int R  = cta * 32 + l;
        f_wih  = W_ih[R];
        f_b    = b_ih[R] + b_hh[R];
        f_wout = W_out[R];
    }
    const float bo = b_out[0];
    const float x0 = inputs[0];
    // streamed tier base (float2): row j at offset j*H2; cols start c512+256
    const float2* wg2 = (const float2*)W_hh + (size_t)RB * H2 + (c512 >> 1) + 128 + l;

    __syncthreads();

    #pragma unroll 1
    for (int t = 0; t < STEPS; t++) {
        // prefetch streamed iter q=0 (h-independent; overlaps the wait)
        float2 buf[8];
        #pragma unroll
        for (int j = 0; j < 8; j++) buf[j] = __ldcg(wg2 + (size_t)j * H2);

        float x = x0;                          // meaningful only in warp 0

        if (t > 0) {
            const unsigned tgt = base + (unsigned)t;
            if (w == 31) {
                const uint4* tp = (const uint4*)g_tag;
                for (;;) {
                    uint4 v = ld_vol_v4(tp + l);
                    bool ok = (v.x >= tgt) & (v.y >= tgt) & (v.z >= tgt) & (v.w >= tgt);
                    if (__all_sync(0xffffffffu, ok)) break;
                    __nanosleep(20);
                }
                __syncwarp();
                if (l == 0) s_ready[0] = (unsigned)t;
            } else {
                while (s_ready[0] < (unsigned)t) { }
            }
            asm volatile("" ::: "memory");

            // finisher gathers x = y_{t-1} while others stage h
            if (w == 0) {
                const float* py = g_party[(t - 1) & 1];
                float pv = __ldcg(py + l) + __ldcg(py + 32 + l)
                         + __ldcg(py + 64 + l) + __ldcg(py + 96 + l);
                pv += __shfl_xor_sync(0xffffffffu, pv, 16);
                pv += __shfl_xor_sync(0xffffffffu, pv, 8);
                pv += __shfl_xor_sync(0xffffffffu, pv, 4);
                pv += __shfl_xor_sync(0xffffffffu, pv, 2);
                pv += __shfl_xor_sync(0xffffffffu, pv, 1);
                x = bo + pv;
                if (cta == 0 && l == 0) out[t - 1] = x;   // ys[t-1]
            }

            // stage h quarter: warp (rg,c) stages 128 floats at c512 + rg*128
            const float4* hb4 = (const float4*)(g_h[(t - 1) & 1] + c512 + rg * 128);
            ((float4*)(h_sw + c512 + rg * 128))[l] = __ldcg(hb4 + l);
        }
        // slice barrier: the 4 warps of slice c (128 threads), barrier 1+c
        asm volatile("bar.sync %0, 128;" :: "r"(1 + c) : "memory");

        // ---- matvec: 8 rows x 512 cols per warp ----
        float acc[8];
        #pragma unroll
        for (int j = 0; j < 8; j++) acc[j] = 0.f;

        const float2* h2 = (const float2*)(h_sw + c512);

        // register tier
        {
            float2 hv = h2[l];
            #pragma unroll
            for (int j = 0; j < 8; j++)
                acc[j] = fmaf(wreg[j].y, hv.y, fmaf(wreg[j].x, hv.x, acc[j]));
        }
        // shared tier (3 iters)
        #pragma unroll
        for (int s = 0; s < 3; s++) {
            float2 hv = h2[32 + 32 * s + l];
            const float2* wp = sw2 + ((w * 3 + s) * 8) * 32 + l;
            #pragma unroll
            for (int j = 0; j < 8; j++) {
                float2 wv = wp[j * 32];
                acc[j] = fmaf(wv.y, hv.y, fmaf(wv.x, hv.x, acc[j]));
            }
        }
        // streamed tier (4 iters, pipelined)
        #pragma unroll
        for (int q = 0; q < 4; q++) {
            float2 hv = h2[128 + 32 * q + l];
            #pragma unroll
            for (int j = 0; j < 8; j++)
                acc[j] = fmaf(buf[j].y, hv.y, fmaf(buf[j].x, hv.x, acc[j]));
            if (q < 3) {
                #pragma unroll
                for (int j = 0; j < 8; j++)
                    buf[j] = __ldcg(wg2 + (q + 1) * 32 + (size_t)j * H2);
            }
        }

        // warp reduce 8 row partials -> s_part[t&1]
        float* spb = s_part + (t & 1) * 256;
        #pragma unroll
        for (int j = 0; j < 8; j++) {
            float v = acc[j];
            v += __shfl_xor_sync(0xffffffffu, v, 16);
            v += __shfl_xor_sync(0xffffffffu, v, 8);
            v += __shfl_xor_sync(0xffffffffu, v, 4);
            v += __shfl_xor_sync(0xffffffffu, v, 2);
            v += __shfl_xor_sync(0xffffffffu, v, 1);
            if (l == 0) spb[(rg * 8 + j) * 8 + c] = v;
        }
        __syncthreads();

        // ---- finisher: combine 8 slice-partials, tanh, publish, tag ----
        if (w == 0) {
            const float4* sp4 = (const float4*)(s_part + (t & 1) * 256 + l * 8);
            float4 a = sp4[0], b4 = sp4[1];
            float dot = ((a.x + a.y) + (a.z + a.w)) + ((b4.x + b4.y) + (b4.z + b4.w));
            float pre  = fmaf(x, f_wih, f_b + dot);
            float hnew = tanhf(pre);
            __stcg(&g_h[t & 1][cta * 32 + l], hnew);

            float pv = hnew * f_wout;
            pv += __shfl_xor_sync(0xffffffffu, pv, 16);
            pv += __shfl_xor_sync(0xffffffffu, pv, 8);
            pv += __shfl_xor_sync(0xffffffffu, pv, 4);
            pv += __shfl_xor_sync(0xffffffffu, pv, 2);
            pv += __shfl_xor_sync(0xffffffffu, pv, 1);
            if (l == 0) __stcg(&g_party[t & 1][cta], pv);

            if (t == STEPS - 1 && out_size >= STEPS + HIDDEN)
                out[STEPS + cta * 32 + l] = hnew;

            __syncwarp();
            asm volatile("fence.acq_rel.gpu;" ::: "memory");   // producer release
            if (l == 0) __stcg(&g_tag[cta], base + (unsigned)t + 1u);
        }
    }

    // final readout ys[STEPS-1]
    if (cta == 0 && w == 0) {
        const unsigned tgt = base + (unsigned)STEPS;
        const uint4* tp = (const uint4*)g_tag;
        for (;;) {
            uint4 v = ld_vol_v4(tp + l);
            bool ok = (v.x >= tgt) & (v.y >= tgt) & (v.z >= tgt) & (v.w >= tgt);
            if (__all_sync(0xffffffffu, ok)) break;
            __nanosleep(20);
        }
        asm volatile("" ::: "memory");
        const float* py = g_party[(STEPS - 1) & 1];
        float pv = __ldcg(py + l) + __ldcg(py + 32 + l)
                 + __ldcg(py + 64 + l) + __ldcg(py + 96 + l);
        pv += __shfl_xor_sync(0xffffffffu, pv, 16);
        pv += __shfl_xor_sync(0xffffffffu, pv, 8);
        pv += __shfl_xor_sync(0xffffffffu, pv, 4);
        pv += __shfl_xor_sync(0xffffffffu, pv, 2);
        pv += __shfl_xor_sync(0xffffffffu, pv, 1);
        if (l == 0) out[STEPS - 1] = bo + pv;
    }
}

extern "C" void kernel_launch(void* const* d_in, const int* in_sizes, int n_in,
                              void* d_out, int out_size)
{
    const float* inputs = (const float*)d_in[0];
    const float* W_ih   = (const float*)d_in[1];
    const float* W_hh   = (const float*)d_in[2];
    const float* b_ih   = (const float*)d_in[3];
    const float* b_hh   = (const float*)d_in[4];
    const float* W_out  = (const float*)d_in[5];
    const float* b_out  = (const float*)d_in[6];
    float* out = (float*)d_out;

    // smem: weights 196608B + h 16384B + parts 2048B + x/ready pad
    const int smem_bytes = (2 * 32 * 3 * 8 * 32 + HIDDEN + 512 + 16)
                           * (int)sizeof(float);
    cudaFuncSetAttribute(rnn_kernel,
                         cudaFuncAttributeMaxDynamicSharedMemorySize, smem_bytes);

    rnn_kernel<<<NCTA, NTH, smem_bytes>>>(
        inputs, W_ih, W_hh, b_ih, b_hh, W_out, b_out, out, out_size);
}

// round 9
// speedup vs baseline: 1.4767x; 1.0743x over previous
#include <cuda_runtime.h>
#include <cstdint>

// Autoregressive RNN, HIDDEN=4096, STEPS=2048.
// 128 persistent CTAs x 1024 threads (32 warps, occ 50%). Warp (rg,c): 8 rows
// x 512-col slice. Weight tiers: cols[0,64) regs (float2), [64,256) smem,
// [256,512) streamed from L2 (float2, pipelined against smem iterations).
// R9: h / tags / y-partials REPLICATED x8 (16 CTAs per replica group) to kill
// L2 same-line serialization; stream loads interleaved with smem tier for
// longer issue-to-use distance; nanosleep in LDS spin to cut MIO pollution.

#define HIDDEN 4096
#define STEPS  2048
#define NCTA   128
#define NTH    1024
#define H2     (HIDDEN / 2)
#define NREP   8

__device__ unsigned g_tagr[NREP][NCTA];      // monotonic across graph replays
__device__ float g_hrep[2][NREP][HIDDEN];    // replicated h ping-pong
__device__ float g_partyr[2][NREP][NCTA];    // replicated y-partials

__device__ __forceinline__ uint4 ld_vol_v4(const uint4* p) {
    uint4 v;
    asm volatile("ld.global.cg.v4.b32 {%0,%1,%2,%3}, [%4];"
                 : "=r"(v.x), "=r"(v.y), "=r"(v.z), "=r"(v.w)
                 : "l"(p) : "memory");
    return v;
}

__global__ __launch_bounds__(NTH, 1)
void rnn_kernel(const float* __restrict__ inputs,
                const float* __restrict__ W_ih,
                const float* __restrict__ W_hh,
                const float* __restrict__ b_ih,
                const float* __restrict__ b_hh,
                const float* __restrict__ W_out,
                const float* __restrict__ b_out,
                float* __restrict__ out, int out_size)
{
    extern __shared__ float smem[];
    float2* sw2   = (float2*)smem;                    // [32][3][8][32] float2
    float*  h_sw  = smem + 2 * (32 * 3 * 8 * 32);     // 4096 floats
    float*  s_part = h_sw + HIDDEN;                   // [2][256]
    float*  s_x    = s_part + 512;
    volatile unsigned* s_ready = (volatile unsigned*)(s_x + 4);

    const int tid = threadIdx.x;
    const int w   = tid >> 5;
    const int l   = tid & 31;
    const int rg  = w >> 3;        // row group 0..3 (8 rows)
    const int c   = w & 7;         // column slice 0..7 (512 cols)
    const int cta = blockIdx.x;
    const int RB  = cta * 32 + rg * 8;
    const int c512 = c * 512;
    const int grp = cta >> 4;      // replica group (16 CTAs each)

    if (tid == 0) s_ready[0] = 0u;
    const unsigned base = __ldcg(&g_tagr[0][cta]);

    // ---- register tier: cols [c512, c512+64), float2 ----
    float2 wreg[8];
    #pragma unroll
    for (int j = 0; j < 8; j++)
        wreg[j] = *(const float2*)&W_hh[(size_t)(RB + j) * HIDDEN + c512 + 2 * l];

    // ---- shared tier: cols [c512+64, c512+256) ----
    for (int s = 0; s < 3; s++)
        for (int j = 0; j < 8; j++)
            sw2[((w * 3 + s) * 8 + j) * 32 + l] =
                *(const float2*)&W_hh[(size_t)(RB + j) * HIDDEN + c512 + 64 + 64 * s + 2 * l];

    for (int idx = tid; idx < HIDDEN; idx += NTH) h_sw[idx] = 0.f;   // h_{-1}=0

    float f_wih = 0.f, f_b = 0.f, f_wout = 0.f;
    if (w == 0) {
        int R  = cta * 32 + l;
        f_wih  = W_ih[R];
        f_b    = b_ih[R] + b_hh[R];
        f_wout = W_out[R];
    }
    const float bo = b_out[0];
    const float x0 = inputs[0];
    const float2* wg2 = (const float2*)W_hh + (size_t)RB * H2 + (c512 >> 1) + 128 + l;

    __syncthreads();

    #pragma unroll 1
    for (int t = 0; t < STEPS; t++) {
        // prefetch streamed q=0 (h-independent; lands during the wait)
        float2 buf[8];
        #pragma unroll
        for (int j = 0; j < 8; j++) buf[j] = __ldcg(wg2 + (size_t)j * H2);

        float x = x0;                          // meaningful only in warp 0

        if (t > 0) {
            const unsigned tgt = base + (unsigned)t;
            if (w == 31) {
                const uint4* tp = (const uint4*)g_tagr[grp];
                for (;;) {
                    uint4 v = ld_vol_v4(tp + l);
                    bool ok = (v.x >= tgt) & (v.y >= tgt) & (v.z >= tgt) & (v.w >= tgt);
                    if (__all_sync(0xffffffffu, ok)) break;
                    __nanosleep(20);
                }
                __syncwarp();
                if (l == 0) s_ready[0] = (unsigned)t;
            } else {
                while (s_ready[0] < (unsigned)t) { __nanosleep(20); }
            }
            asm volatile("" ::: "memory");

            // finisher gathers x = y_{t-1} from own replica
            if (w == 0) {
                const float* py = g_partyr[(t - 1) & 1][grp];
                float pv = __ldcg(py + l) + __ldcg(py + 32 + l)
                         + __ldcg(py + 64 + l) + __ldcg(py + 96 + l);
                pv += __shfl_xor_sync(0xffffffffu, pv, 16);
                pv += __shfl_xor_sync(0xffffffffu, pv, 8);
                pv += __shfl_xor_sync(0xffffffffu, pv, 4);
                pv += __shfl_xor_sync(0xffffffffu, pv, 2);
                pv += __shfl_xor_sync(0xffffffffu, pv, 1);
                x = bo + pv;
                if (cta == 0 && l == 0) out[t - 1] = x;   // ys[t-1]
            }

            // stage h quarter from own replica
            const float4* hb4 = (const float4*)(g_hrep[(t - 1) & 1][grp] + c512 + rg * 128);
            ((float4*)(h_sw + c512 + rg * 128))[l] = __ldcg(hb4 + l);
        }
        // slice barrier: 4 warps of slice c
        asm volatile("bar.sync %0, 128;" :: "r"(1 + c) : "memory");

        // ---- matvec: 8 rows x 512 cols; stream iters interleaved with smem
        float acc[8];
        #pragma unroll
        for (int j = 0; j < 8; j++) acc[j] = 0.f;

        const float2* h2 = (const float2*)(h_sw + c512);

        // register tier
        {
            float2 hv = h2[l];
            #pragma unroll
            for (int j = 0; j < 8; j++)
                acc[j] = fmaf(wreg[j].y, hv.y, fmaf(wreg[j].x, hv.x, acc[j]));
        }
        // stream q0 FMA, then load q1
        {
            float2 hv = h2[128 + l];
            #pragma unroll
            for (int j = 0; j < 8; j++)
                acc[j] = fmaf(buf[j].y, hv.y, fmaf(buf[j].x, hv.x, acc[j]));
            #pragma unroll
            for (int j = 0; j < 8; j++) buf[j] = __ldcg(wg2 + 32 + (size_t)j * H2);
        }
        // smem s0
        {
            float2 hv = h2[32 + l];
            const float2* wp = sw2 + ((w * 3 + 0) * 8) * 32 + l;
            #pragma unroll
            for (int j = 0; j < 8; j++) {
                float2 wv = wp[j * 32];
                acc[j] = fmaf(wv.y, hv.y, fmaf(wv.x, hv.x, acc[j]));
            }
        }
        // stream q1 FMA, load q2
        {
            float2 hv = h2[160 + l];
            #pragma unroll
            for (int j = 0; j < 8; j++)
                acc[j] = fmaf(buf[j].y, hv.y, fmaf(buf[j].x, hv.x, acc[j]));
            #pragma unroll
            for (int j = 0; j < 8; j++) buf[j] = __ldcg(wg2 + 64 + (size_t)j * H2);
        }
        // smem s1
        {
            float2 hv = h2[64 + l];
            const float2* wp = sw2 + ((w * 3 + 1) * 8) * 32 + l;
            #pragma unroll
            for (int j = 0; j < 8; j++) {
                float2 wv = wp[j * 32];
                acc[j] = fmaf(wv.y, hv.y, fmaf(wv.x, hv.x, acc[j]));
            }
        }
        // stream q2 FMA, load q3
        {
            float2 hv = h2[192 + l];
            #pragma unroll
            for (int j = 0; j < 8; j++)
                acc[j] = fmaf(buf[j].y, hv.y, fmaf(buf[j].x, hv.x, acc[j]));
            #pragma unroll
            for (int j = 0; j < 8; j++) buf[j] = __ldcg(wg2 + 96 + (size_t)j * H2);
        }
        // smem s2
        {
            float2 hv = h2[96 + l];
            const float2* wp = sw2 + ((w * 3 + 2) * 8) * 32 + l;
            #pragma unroll
            for (int j = 0; j < 8; j++) {
                float2 wv = wp[j * 32];
                acc[j] = fmaf(wv.y, hv.y, fmaf(wv.x, hv.x, acc[j]));
            }
        }
        // stream q3 FMA
        {
            float2 hv = h2[224 + l];
            #pragma unroll
            for (int j = 0; j < 8; j++)
                acc[j] = fmaf(buf[j].y, hv.y, fmaf(buf[j].x, hv.x, acc[j]));
        }

        // warp reduce 8 row partials -> s_part[t&1]
        float* spb = s_part + (t & 1) * 256;
        #pragma unroll
        for (int j = 0; j < 8; j++) {
            float v = acc[j];
            v += __shfl_xor_sync(0xffffffffu, v, 16);
            v += __shfl_xor_sync(0xffffffffu, v, 8);
            v += __shfl_xor_sync(0xffffffffu, v, 4);
            v += __shfl_xor_sync(0xffffffffu, v, 2);
            v += __shfl_xor_sync(0xffffffffu, v, 1);
            if (l == 0) spb[(rg * 8 + j) * 8 + c] = v;
        }
        __syncthreads();

        // ---- finisher: combine, tanh, publish to ALL replicas, tag ----
        if (w == 0) {
            const float4* sp4 = (const float4*)(s_part + (t & 1) * 256 + l * 8);
            float4 a = sp4[0], b4 = sp4[1];
            float dot = ((a.x + a.y) + (a.z + a.w)) + ((b4.x + b4.y) + (b4.z + b4.w));
            float pre  = fmaf(x, f_wih, f_b + dot);
            float hnew = tanhf(pre);
            #pragma unroll
            for (int rep = 0; rep < NREP; rep++)
                __stcg(&g_hrep[t & 1][rep][cta * 32 + l], hnew);

            float pv = hnew * f_wout;
            pv += __shfl_xor_sync(0xffffffffu, pv, 16);
            pv += __shfl_xor_sync(0xffffffffu, pv, 8);
            pv += __shfl_xor_sync(0xffffffffu, pv, 4);
            pv += __shfl_xor_sync(0xffffffffu, pv, 2);
            pv += __shfl_xor_sync(0xffffffffu, pv, 1);
            if (l < NREP) __stcg(&g_partyr[t & 1][l][cta], pv);

            if (t == STEPS - 1 && out_size >= STEPS + HIDDEN)
                out[STEPS + cta * 32 + l] = hnew;

            __syncwarp();
            asm volatile("fence.acq_rel.gpu;" ::: "memory");   // producer release
            if (l < NREP) __stcg(&g_tagr[l][cta], base + (unsigned)t + 1u);
        }
    }

    // final readout ys[STEPS-1]
    if (cta == 0 && w == 0) {
        const unsigned tgt = base + (unsigned)STEPS;
        const uint4* tp = (const uint4*)g_tagr[0];
        for (;;) {
            uint4 v = ld_vol_v4(tp + l);
            bool ok = (v.x >= tgt) & (v.y >= tgt) & (v.z >= tgt) & (v.w >= tgt);
            if (__all_sync(0xffffffffu, ok)) break;
            __nanosleep(20);
        }
        asm volatile("" ::: "memory");
        const float* py = g_partyr[(STEPS - 1) & 1][0];
        float pv = __ldcg(py + l) + __ldcg(py + 32 + l)
                 + __ldcg(py + 64 + l) + __ldcg(py + 96 + l);
        pv += __shfl_xor_sync(0xffffffffu, pv, 16);
        pv += __shfl_xor_sync(0xffffffffu, pv, 8);
        pv += __shfl_xor_sync(0xffffffffu, pv, 4);
        pv += __shfl_xor_sync(0xffffffffu, pv, 2);
        pv += __shfl_xor_sync(0xffffffffu, pv, 1);
        if (l == 0) out[STEPS - 1] = bo + pv;
    }
}

extern "C" void kernel_launch(void* const* d_in, const int* in_sizes, int n_in,
                              void* d_out, int out_size)
{
    const float* inputs = (const float*)d_in[0];
    const float* W_ih   = (const float*)d_in[1];
    const float* W_hh   = (const float*)d_in[2];
    const float* b_ih   = (const float*)d_in[3];
    const float* b_hh   = (const float*)d_in[4];
    const float* W_out  = (const float*)d_in[5];
    const float* b_out  = (const float*)d_in[6];
    float* out = (float*)d_out;

    const int smem_bytes = (2 * 32 * 3 * 8 * 32 + HIDDEN + 512 + 16)
                           * (int)sizeof(float);
    cudaFuncSetAttribute(rnn_kernel,
                         cudaFuncAttributeMaxDynamicSharedMemorySize, smem_bytes);

    rnn_kernel<<<NCTA, NTH, smem_bytes>>>(
        inputs, W_ih, W_hh, b_ih, b_hh, W_out, b_out, out, out_size);
}

// round 11
// speedup vs baseline: 2.8329x; 1.9184x over previous
#include <cuda_runtime.h>
#include <cstdint>

// Autoregressive RNN, HIDDEN=4096, STEPS=2048.
// 128 persistent CTAs x 1024 threads (occ 50%). Warp (rg,c): 8 rows x 512 cols.
// Weight tiers: cols[0,64) regs, [64,256) smem, [256,512) streamed L2.
// R10: FUSED (tag,value) uint2 pairs for h and y-partials — the polling load
// carries the data. No gpu fence, no poll warp, no smem epoch, one fewer L2
// round trip per step. Replicated x8. Epoch counter gives replay-safe tags.

#define HIDDEN 4096
#define STEPS  2048
#define NCTA   128
#define NTH    1024
#define H2     (HIDDEN / 2)
#define NREP   8

__device__ unsigned g_epoch;                  // launches completed (replay-safe)
__device__ uint2 g_hpair[2][NREP][HIDDEN];    // (tag, h-bits) pairs, parity x replicas
__device__ uint2 g_ppair[2][NREP][NCTA];      // (tag, y-partial-bits) pairs

__device__ __forceinline__ unsigned ld_vol_u32(const unsigned* p) {
    unsigned v;
    asm volatile("ld.global.cg.b32 %0, [%1];" : "=r"(v) : "l"(p) : "memory");
    return v;
}
__device__ __forceinline__ uint4 ld_vol_v4(const uint4* p) {
    uint4 v;
    asm volatile("ld.global.cg.v4.b32 {%0,%1,%2,%3}, [%4];"
                 : "=r"(v.x), "=r"(v.y), "=r"(v.z), "=r"(v.w)
                 : "l"(p) : "memory");
    return v;
}
__device__ __forceinline__ void st_cg_v2(uint2* p, unsigned a, unsigned b) {
    asm volatile("st.global.cg.v2.u32 [%0], {%1,%2};"
                 :: "l"(p), "r"(a), "r"(b) : "memory");
}

__global__ __launch_bounds__(NTH, 1)
void rnn_kernel(const float* __restrict__ inputs,
                const float* __restrict__ W_ih,
                const float* __restrict__ W_hh,
                const float* __restrict__ b_ih,
                const float* __restrict__ b_hh,
                const float* __restrict__ W_out,
                const float* __restrict__ b_out,
                float* __restrict__ out, int out_size)
{
    extern __shared__ float smem[];
    float2* sw2   = (float2*)smem;                    // [32][3][8][32] float2
    float*  h_sw  = smem + 2 * (32 * 3 * 8 * 32);     // 4096 floats
    float*  s_part = h_sw + HIDDEN;                   // [2][256]

    const int tid = threadIdx.x;
    const int w   = tid >> 5;
    const int l   = tid & 31;
    const int rg  = w >> 3;        // row group 0..3
    const int c   = w & 7;         // column slice 0..7
    const int cta = blockIdx.x;
    const int RB  = cta * 32 + rg * 8;
    const int c512 = c * 512;
    const int grp = cta >> 4;      // replica group (16 CTAs)

    const unsigned ep   = ld_vol_u32(&g_epoch);
    const unsigned base = ep * (unsigned)STEPS;

    // ---- register tier: cols [c512, c512+64) ----
    float2 wreg[8];
    #pragma unroll
    for (int j = 0; j < 8; j++)
        wreg[j] = *(const float2*)&W_hh[(size_t)(RB + j) * HIDDEN + c512 + 2 * l];

    // ---- shared tier: cols [c512+64, c512+256) ----
    for (int s = 0; s < 3; s++)
        for (int j = 0; j < 8; j++)
            sw2[((w * 3 + s) * 8 + j) * 32 + l] =
                *(const float2*)&W_hh[(size_t)(RB + j) * HIDDEN + c512 + 64 + 64 * s + 2 * l];

    for (int idx = tid; idx < HIDDEN; idx += NTH) h_sw[idx] = 0.f;   // h_{-1}=0

    float f_wih = 0.f, f_b = 0.f, f_wout = 0.f;
    if (w == 0) {
        int R  = cta * 32 + l;
        f_wih  = W_ih[R];
        f_b    = b_ih[R] + b_hh[R];
        f_wout = W_out[R];
    }
    const float bo = b_out[0];
    const float x0 = inputs[0];
    const float2* wg2 = (const float2*)W_hh + (size_t)RB * H2 + (c512 >> 1) + 128 + l;

    __syncthreads();

    #pragma unroll 1
    for (int t = 0; t < STEPS; t++) {
        // prefetch streamed q=0 (h-independent; lands during the wait)
        float2 buf[8];
        #pragma unroll
        for (int j = 0; j < 8; j++) buf[j] = __ldcg(wg2 + (size_t)j * H2);

        float x = x0;                          // meaningful only in warp 0

        if (t > 0) {
            const unsigned tgt = base + (unsigned)t;

            // ---- stage h quarter via fused pairs: poll carries the data ----
            const uint4* hp = (const uint4*)&g_hpair[(t - 1) & 1][grp][c512 + rg * 128];
            uint4 a, b4;
            for (;;) {
                a  = ld_vol_v4(hp + l);        // pairs 2l, 2l+1
                b4 = ld_vol_v4(hp + 32 + l);   // pairs 64+2l, 64+2l+1
                bool ok = (a.x >= tgt) & (a.z >= tgt) & (b4.x >= tgt) & (b4.z >= tgt);
                if (__all_sync(0xffffffffu, ok)) break;
                __nanosleep(40);
            }
            float2* dst = (float2*)(h_sw + c512 + rg * 128);
            dst[l]      = make_float2(__uint_as_float(a.y),  __uint_as_float(a.w));
            dst[32 + l] = make_float2(__uint_as_float(b4.y), __uint_as_float(b4.w));

            // ---- finisher gathers x = y_{t-1} via fused party pairs ----
            if (w == 0) {
                const uint4* pp = (const uint4*)&g_ppair[(t - 1) & 1][grp][0];
                uint4 pa, pb;
                for (;;) {
                    pa = ld_vol_v4(pp + l);
                    pb = ld_vol_v4(pp + 32 + l);
                    bool ok = (pa.x >= tgt) & (pa.z >= tgt) & (pb.x >= tgt) & (pb.z >= tgt);
                    if (__all_sync(0xffffffffu, ok)) break;
                    __nanosleep(40);
                }
                float pv = __uint_as_float(pa.y) + __uint_as_float(pa.w)
                         + __uint_as_float(pb.y) + __uint_as_float(pb.w);
                pv += __shfl_xor_sync(0xffffffffu, pv, 16);
                pv += __shfl_xor_sync(0xffffffffu, pv, 8);
                pv += __shfl_xor_sync(0xffffffffu, pv, 4);
                pv += __shfl_xor_sync(0xffffffffu, pv, 2);
                pv += __shfl_xor_sync(0xffffffffu, pv, 1);
                x = bo + pv;
                if (cta == 0 && l == 0) out[t - 1] = x;   // ys[t-1]
            }
        }
        // slice barrier: 4 warps of slice c
        asm volatile("bar.sync %0, 128;" :: "r"(1 + c) : "memory");

        // ---- matvec: 8 rows x 512 cols; stream interleaved with smem ----
        float acc[8];
        #pragma unroll
        for (int j = 0; j < 8; j++) acc[j] = 0.f;

        const float2* h2 = (const float2*)(h_sw + c512);

        {   // register tier
            float2 hv = h2[l];
            #pragma unroll
            for (int j = 0; j < 8; j++)
                acc[j] = fmaf(wreg[j].y, hv.y, fmaf(wreg[j].x, hv.x, acc[j]));
        }
        {   // stream q0, load q1
            float2 hv = h2[128 + l];
            #pragma unroll
            for (int j = 0; j < 8; j++)
                acc[j] = fmaf(buf[j].y, hv.y, fmaf(buf[j].x, hv.x, acc[j]));
            #pragma unroll
            for (int j = 0; j < 8; j++) buf[j] = __ldcg(wg2 + 32 + (size_t)j * H2);
        }
        {   // smem s0
            float2 hv = h2[32 + l];
            const float2* wp = sw2 + ((w * 3 + 0) * 8) * 32 + l;
            #pragma unroll
            for (int j = 0; j < 8; j++) {
                float2 wv = wp[j * 32];
                acc[j] = fmaf(wv.y, hv.y, fmaf(wv.x, hv.x, acc[j]));
            }
        }
        {   // stream q1, load q2
            float2 hv = h2[160 + l];
            #pragma unroll
            for (int j = 0; j < 8; j++)
                acc[j] = fmaf(buf[j].y, hv.y, fmaf(buf[j].x, hv.x, acc[j]));
            #pragma unroll
            for (int j = 0; j < 8; j++) buf[j] = __ldcg(wg2 + 64 + (size_t)j * H2);
        }
        {   // smem s1
            float2 hv = h2[64 + l];
            const float2* wp = sw2 + ((w * 3 + 1) * 8) * 32 + l;
            #pragma unroll
            for (int j = 0; j < 8; j++) {
                float2 wv = wp[j * 32];
                acc[j] = fmaf(wv.y, hv.y, fmaf(wv.x, hv.x, acc[j]));
            }
        }
        {   // stream q2, load q3
            float2 hv = h2[192 + l];
            #pragma unroll
            for (int j = 0; j < 8; j++)
                acc[j] = fmaf(buf[j].y, hv.y, fmaf(buf[j].x, hv.x, acc[j]));
            #pragma unroll
            for (int j = 0; j < 8; j++) buf[j] = __ldcg(wg2 + 96 + (size_t)j * H2);
        }
        {   // smem s2
            float2 hv = h2[96 + l];
            const float2* wp = sw2 + ((w * 3 + 2) * 8) * 32 + l;
            #pragma unroll
            for (int j = 0; j < 8; j++) {
                float2 wv = wp[j * 32];
                acc[j] = fmaf(wv.y, hv.y, fmaf(wv.x, hv.x, acc[j]));
            }
        }
        {   // stream q3
            float2 hv = h2[224 + l];
            #pragma unroll
            for (int j = 0; j < 8; j++)
                acc[j] = fmaf(buf[j].y, hv.y, fmaf(buf[j].x, hv.x, acc[j]));
        }

        // warp reduce 8 row partials -> s_part[t&1]
        float* spb = s_part + (t & 1) * 256;
        #pragma unroll
        for (int j = 0; j < 8; j++) {
            float v = acc[j];
            v += __shfl_xor_sync(0xffffffffu, v, 16);
            v += __shfl_xor_sync(0xffffffffu, v, 8);
            v += __shfl_xor_sync(0xffffffffu, v, 4);
            v += __shfl_xor_sync(0xffffffffu, v, 2);
            v += __shfl_xor_sync(0xffffffffu, v, 1);
            if (l == 0) spb[(rg * 8 + j) * 8 + c] = v;
        }
        __syncthreads();

        // ---- finisher: combine, tanh, publish fused pairs (no fence) ----
        if (w == 0) {
            const float4* sp4 = (const float4*)(s_part + (t & 1) * 256 + l * 8);
            float4 a = sp4[0], b4 = sp4[1];
            float dot = ((a.x + a.y) + (a.z + a.w)) + ((b4.x + b4.y) + (b4.z + b4.w));
            float pre  = fmaf(x, f_wih, f_b + dot);
            float hnew = tanhf(pre);

            const unsigned ntag = base + (unsigned)t + 1u;
            const unsigned hbits = __float_as_uint(hnew);
            #pragma unroll
            for (int rep = 0; rep < NREP; rep++)
                st_cg_v2(&g_hpair[t & 1][rep][cta * 32 + l], ntag, hbits);

            float pv = hnew * f_wout;
            pv += __shfl_xor_sync(0xffffffffu, pv, 16);
            pv += __shfl_xor_sync(0xffffffffu, pv, 8);
            pv += __shfl_xor_sync(0xffffffffu, pv, 4);
            pv += __shfl_xor_sync(0xffffffffu, pv, 2);
            pv += __shfl_xor_sync(0xffffffffu, pv, 1);
            if (l < NREP)
                st_cg_v2(&g_ppair[t & 1][l][cta], ntag, __float_as_uint(pv));

            if (t == STEPS - 1 && out_size >= STEPS + HIDDEN)
                out[STEPS + cta * 32 + l] = hnew;
        }
    }

    // final readout ys[STEPS-1]; then CTA0 bumps the epoch
    if (cta == 0 && w == 0) {
        const unsigned tgt = base + (unsigned)STEPS;
        const uint4* pp = (const uint4*)&g_ppair[(STEPS - 1) & 1][0][0];
        uint4 pa, pb;
        for (;;) {
            pa = ld_vol_v4(pp + l);
            pb = ld_vol_v4(pp + 32 + l);
            bool ok = (pa.x >= tgt) & (pa.z >= tgt) & (pb.x >= tgt) & (pb.z >= tgt);
            if (__all_sync(0xffffffffu, ok)) break;
            __nanosleep(40);
        }
        float pv = __uint_as_float(pa.y) + __uint_as_float(pa.w)
                 + __uint_as_float(pb.y) + __uint_as_float(pb.w);
        pv += __shfl_xor_sync(0xffffffffu, pv, 16);
        pv += __shfl_xor_sync(0xffffffffu, pv, 8);
        pv += __shfl_xor_sync(0xffffffffu, pv, 4);
        pv += __shfl_xor_sync(0xffffffffu, pv, 2);
        pv += __shfl_xor_sync(0xffffffffu, pv, 1);
        if (l == 0) {
            out[STEPS - 1] = bo + pv;
            asm volatile("st.global.cg.b32 [%0], %1;"
                         :: "l"(&g_epoch), "r"(ep + 1u) : "memory");
        }
    }
}

extern "C" void kernel_launch(void* const* d_in, const int* in_sizes, int n_in,
                              void* d_out, int out_size)
{
    const float* inputs = (const float*)d_in[0];
    const float* W_ih   = (const float*)d_in[1];
    const float* W_hh   = (const float*)d_in[2];
    const float* b_ih   = (const float*)d_in[3];
    const float* b_hh   = (const float*)d_in[4];
    const float* W_out  = (const float*)d_in[5];
    const float* b_out  = (const float*)d_in[6];
    float* out = (float*)d_out;

    const int smem_bytes = (2 * 32 * 3 * 8 * 32 + HIDDEN + 512 + 8)
                           * (int)sizeof(float);
    cudaFuncSetAttribute(rnn_kernel,
                         cudaFuncAttributeMaxDynamicSharedMemorySize, smem_bytes);

    rnn_kernel<<<NCTA, NTH, smem_bytes>>>(
        inputs, W_ih, W_hh, b_ih, b_hh, W_out, b_out, out, out_size);
}